// round 15
// baseline (speedup 1.0000x reference)
#include <cuda_runtime.h>
#include <cuda_bf16.h>
#include <stdint.h>
#include <math.h>

#define NB 64
#define NH 1024
#define NV 32000
#define NT 31
#define NBLK 250   // sampler n-slices (32000/128)
#define NPAIR 16   // t-pairs (M=128 rows each)
#define NKC 64     // k chunks of 16

// -------- device scratch --------
__device__ float g_W1p[512 * 4096];
__device__ float g_W2p[1024 * 4096];
__device__ float g_hs[(NT + 1) * NB * NH];
__device__ float g_c[NB * NH];
__device__ float4 g_pm[NT * NBLK * NB];
__device__ float4 g_pa[NT * NBLK * NB];
// chunked layouts: [k/16][row or n][16] bf16 -> per-(chunk,slice) tile contiguous
__device__ __align__(16) __nv_bfloat16 g_Ahi[NKC * 2048 * 16];
__device__ __align__(16) __nv_bfloat16 g_Alo[NKC * 2048 * 16];
__device__ __align__(16) __nv_bfloat16 g_Bhi[(size_t)NKC * NV * 16];
__device__ __align__(16) __nv_bfloat16 g_Blo[(size_t)NKC * NV * 16];
__device__ float g_logitsA[(size_t)NT * NB * NV];

__device__ __forceinline__ float negInf() { return __int_as_float(0xff800000); }

// ---- packed f32x2 FMA (for gemmG) ----
__device__ __forceinline__ unsigned long long pk2(float x) {
    unsigned long long r;
    asm("mov.b64 %0, {%1, %1};" : "=l"(r) : "f"(x));
    return r;
}
__device__ __forceinline__ void fma2(unsigned long long& c, unsigned long long a,
                                     unsigned long long b) {
    asm("fma.rn.f32x2 %0, %1, %2, %0;" : "+l"(c) : "l"(a), "l"(b));
}
__device__ __forceinline__ float lo32(unsigned long long v) {
    return __uint_as_float((unsigned)v);
}
__device__ __forceinline__ float hi32(unsigned long long v) {
    return __uint_as_float((unsigned)(v >> 32));
}

// ---- cp.async scalar (gemmG) ----
#define CP4(dst, src) \
    asm volatile("cp.async.ca.shared.global [%0], [%1], 4;" :: "r"(dst), "l"(src))
#define CP_COMMIT() asm volatile("cp.async.commit_group;")
#define CP_WAIT2()  asm volatile("cp.async.wait_group 2;")

// ---- bulk copy + mbarrier (base sm_90 features, no 'a' suffix needed) ----
#define BULK(dst, src, sz, mbar) \
    asm volatile("cp.async.bulk.shared::cluster.global.mbarrier::complete_tx::bytes " \
                 "[%0], [%1], %2, [%3];" \
                 :: "r"(dst), "l"(src), "r"(sz), "r"(mbar) : "memory")
#define MBAR_INIT(a, c) \
    asm volatile("mbarrier.init.shared.b64 [%0], %1;" :: "r"(a), "r"(c) : "memory")
#define MBAR_EXPECT(a, b) \
    asm volatile("mbarrier.arrive.expect_tx.shared.b64 _, [%0], %1;" \
                 :: "r"(a), "r"(b) : "memory")
#define MBAR_WAIT(mbar, par) do { \
    uint32_t _m = (mbar), _p = (par), _d; \
    asm volatile("{\n\t.reg .pred p;\n\t" \
        "mbarrier.try_wait.parity.acquire.cta.shared::cta.b64 p, [%1], %2;\n\t" \
        "selp.b32 %0, 1, 0, p;\n\t}" : "=r"(_d) : "r"(_m), "r"(_p) : "memory"); \
    if (!_d) { \
        asm volatile("{\n\t.reg .pred P1;\n\t" \
            "WL_%=:\n\t" \
            "mbarrier.try_wait.parity.acquire.cta.shared::cta.b64 P1, [%0], %1, 0x989680;\n\t" \
            "@P1 bra.uni WD_%=;\n\t" \
            "bra.uni WL_%=;\n\t" \
            "WD_%=:\n\t}" :: "r"(_m), "r"(_p) : "memory"); \
    } \
} while (0)

// ---- warp-level tensor core MMA (sm_80+ baseline HMMA) ----
__device__ __forceinline__ void mma16816(float* c, const uint32_t* a,
                                         const uint32_t* b) {
    asm volatile(
        "mma.sync.aligned.m16n8k16.row.col.f32.bf16.bf16.f32 "
        "{%0,%1,%2,%3}, {%4,%5,%6,%7}, {%8,%9}, {%0,%1,%2,%3};"
        : "+f"(c[0]), "+f"(c[1]), "+f"(c[2]), "+f"(c[3])
        : "r"(a[0]), "r"(a[1]), "r"(a[2]), "r"(a[3]), "r"(b[0]), "r"(b[1]));
}

// exact JAX threefry2x32
__device__ __forceinline__ void tf2x32(uint32_t k0, uint32_t k1,
                                       uint32_t x0, uint32_t x1,
                                       uint32_t& o0, uint32_t& o1) {
    uint32_t k2 = k0 ^ k1 ^ 0x1BD11BDAu;
    x0 += k0; x1 += k1;
#define TFR(r) { x0 += x1; x1 = (x1 << (r)) | (x1 >> (32 - (r))); x1 ^= x0; }
    TFR(13) TFR(15) TFR(26) TFR(6)
    x0 += k1; x1 += k2 + 1u;
    TFR(17) TFR(29) TFR(16) TFR(24)
    x0 += k2; x1 += k0 + 2u;
    TFR(13) TFR(15) TFR(26) TFR(6)
    x0 += k0; x1 += k1 + 3u;
    TFR(17) TFR(29) TFR(16) TFR(24)
    x0 += k1; x1 += k2 + 4u;
    TFR(13) TFR(15) TFR(26) TFR(6)
    x0 += k2; x1 += k0 + 5u;
#undef TFR
    o0 = x0; o1 = x1;
}

__device__ __forceinline__ float u01(uint32_t b) {
    float f = __uint_as_float((b >> 9) | 0x3f800000u) - 1.0f;
    return fmaxf(f, 1.17549435e-38f);
}
__device__ __forceinline__ float exact_g(float u) {
    return (float)(-log(-log((double)u)));
}

__device__ __forceinline__ void softmerge(float& m, float& S, float& T,
                                          float m2, float S2, float T2) {
    if (S2 == 0.f) return;
    if (S == 0.f) { m = m2; S = S2; T = T2; return; }
    if (m2 > m) {
        float t;
        t = m; m = m2; m2 = t;
        t = S; S = S2; S2 = t;
        t = T; T = T2; T2 = t;
    }
    float e = expf(m2 - m);
    S += S2 * e;
    T += (T2 + (m2 - m) * S2) * e;
}

__global__ void k_init() {
    int i = blockIdx.x * blockDim.x + threadIdx.x;
    if (i < NB * NH) g_c[i] = 0.f;
}
__global__ void k_init2(float* __restrict__ out) {
    int i = blockIdx.x * blockDim.x + threadIdx.x;
    if (i < 3 * NB * 2 * NT) out[i] = 0.f;
}

__global__ void k_prep(const float* __restrict__ Wx1, const float* __restrict__ Wx2,
                       const float* __restrict__ Wh2) {
    int idx = blockIdx.x * blockDim.x + threadIdx.x;
    int k = idx >> 12, col = idx & 4095;
    int j = col >> 2, q = col & 3;
    int src = (k << 12) + (q << 10) + j;
    g_W2p[idx] = Wx2[src] + Wh2[src];
    if (k < 512) g_W1p[idx] = Wx1[src];
}

// Wd[k][n] -> chunked-transposed hi/lo: g_B*[(k/16)*NV + n][k%16]
__global__ void k_w2b(const float* __restrict__ Wd) {
    __shared__ float tile[32][33];
    int nt = blockIdx.x;   // 0..999
    int kt = blockIdx.y;   // 0..31
    int tx = threadIdx.x, ty = threadIdx.y;
    for (int r = ty; r < 32; r += 8)
        tile[r][tx] = Wd[(size_t)(kt * 32 + r) * NV + nt * 32 + tx];
    __syncthreads();
    int k2 = kt * 32 + tx;
    size_t base = ((size_t)(k2 >> 4) * NV) * 16 + (k2 & 15);
    for (int r = ty; r < 32; r += 8) {
        float v = tile[tx][r];
        __nv_bfloat16 hi = __float2bfloat16(v);
        __nv_bfloat16 lo = __float2bfloat16(v - __bfloat162float(hi));
        size_t o = base + (size_t)(nt * 32 + r) * 16;
        g_Bhi[o] = hi;
        g_Blo[o] = lo;
    }
}

// h states -> chunked stacked pairs: g_A*[(k/16)*2048 + p*128 + r][k%16]
__global__ void k_h2b() {
    int idx = blockIdx.x * blockDim.x + threadIdx.x;   // < 64*2048*16 = 2M
    if (idx >= NKC * 2048 * 16) return;
    int c = idx >> 15;
    int row = (idx >> 4) & 2047;
    int kk = idx & 15;
    int p = row >> 7, r = row & 127;
    int t_idx = (r < 64) ? (2 * p + 1) : (2 * p + 2 > 31 ? 31 : 2 * p + 2);
    float v = g_hs[(size_t)t_idx * NB * NH + (r & 63) * NH + c * 16 + kk];
    __nv_bfloat16 hi = __float2bfloat16(v);
    g_Ahi[idx] = hi;
    g_Alo[idx] = __float2bfloat16(v - __bfloat162float(hi));
}

// Fused gate GEMM + LSTM pointwise (R13 version, measured 27us)
__global__ __launch_bounds__(256, 2) void gemmG(const float* __restrict__ A,
                                                const float* __restrict__ W,
                                                const float* __restrict__ bias,
                                                float* __restrict__ hout,
                                                int K) {
    __shared__ float As[2][16][64];
    __shared__ float Bs[4][16][16];
    const int tid = threadIdx.x;
    const int row = tid & 63;
    const int jj  = tid >> 6;
    const int j0  = blockIdx.x * 4;
    const int c0  = blockIdx.x * 16;
    const int ar = tid >> 2, ak = (tid & 3) * 4;
    const int kr = tid >> 4, cc = tid & 15;
    const int NC = K / 16;

    unsigned long long aif = 0, ago = 0;

    const float* bsrc = W + (size_t)kr * 4096 + c0 + cc;
    uint32_t bBase = (uint32_t)__cvta_generic_to_shared(&Bs[0][kr][cc]);

#pragma unroll
    for (int s = 0; s < 3; s++) {
        if (s < NC) CP4(bBase + s * 1024, bsrc + (size_t)s * 16 * 4096);
        CP_COMMIT();
    }
    float4 paN;
    {
        float4 p0 = *(const float4*)(A + ar * K + ak);
        As[0][ak + 0][ar] = p0.x; As[0][ak + 1][ar] = p0.y;
        As[0][ak + 2][ar] = p0.z; As[0][ak + 3][ar] = p0.w;
        paN = *(const float4*)(A + ar * K + 16 + ak);
    }

    for (int c = 0; c < NC; c++) {
        CP_WAIT2();
        __syncthreads();
        if (c + 1 < NC) {
            int b = (c + 1) & 1;
            As[b][ak + 0][ar] = paN.x; As[b][ak + 1][ar] = paN.y;
            As[b][ak + 2][ar] = paN.z; As[b][ak + 3][ar] = paN.w;
        }
        if (c + 2 < NC) paN = *(const float4*)(A + ar * K + (c + 2) * 16 + ak);
        if (c + 3 < NC) CP4(bBase + ((c + 3) & 3) * 1024,
                            bsrc + (size_t)(c + 3) * 16 * 4096);
        CP_COMMIT();
        int cur = c & 1, cb = c & 3;
#pragma unroll
        for (int k = 0; k < 16; k++) {
            unsigned long long ap = pk2(As[cur][k][row]);
            ulonglong2 bA = *(const ulonglong2*)&Bs[cb][k][jj * 4];
            fma2(aif, ap, bA.x);
            fma2(ago, ap, bA.y);
        }
    }

    int j = j0 + jj;
    float zi = __fadd_rn(lo32(aif), bias[j]);
    float zf = __fadd_rn(hi32(aif), bias[1024 + j]);
    float zg = __fadd_rn(lo32(ago), bias[2048 + j]);
    float zo = __fadd_rn(hi32(ago), bias[3072 + j]);
    float si = 1.f / (1.f + expf(-zi));
    float sf = 1.f / (1.f + expf(-zf));
    float so = 1.f / (1.f + expf(-zo));
    int ci = row * NH + j;
    float cn = __fadd_rn(__fmul_rn(sf, g_c[ci]), __fmul_rn(si, zg));
    g_c[ci] = cn;
    hout[ci] = __fmul_rn(so, cn);
}

// Tensor-core logits: D(128x128) = Apair(128x1024) @ Wd-slice, bf16 hi/lo
// 3-term split via mma.sync m16n8k16. 4-stage cp.async.bulk ring + mbarrier.
__global__ __launch_bounds__(256, 2) void gemmF_mma(const float* __restrict__ bias) {
    extern __shared__ char dsm[];
    __shared__ float sb[128];
    __shared__ __align__(8) unsigned long long mb[4];

    const int p = blockIdx.x;          // t-pair
    const int n0 = blockIdx.y * 128;   // col slice
    const int tid = threadIdx.x;
    const int w = tid >> 5, lane = tid & 31;
    const int wm = w & 1;              // m-half (64 rows)
    const int wn = w >> 1;             // n-quarter (32 cols)
    const int g = lane >> 2, tg = lane & 3;

    uint32_t sbase = (uint32_t)__cvta_generic_to_shared(dsm);
    uint32_t ab = (sbase + 1023) & ~1023u;
    char* dsg = dsm + (ab - sbase);
    uint32_t mbarA = (uint32_t)__cvta_generic_to_shared(&mb[0]);

    if (tid < 128) sb[tid] = bias[n0 + tid];
    if (tid == 0) {
#pragma unroll
        for (int s = 0; s < 4; s++) MBAR_INIT(mbarA + s * 8, 1);
    }
    __syncthreads();

    const char* srcAh = (const char*)g_Ahi + (size_t)p * 128 * 32;
    const char* srcAl = (const char*)g_Alo + (size_t)p * 128 * 32;
    const char* srcBh = (const char*)g_Bhi + (size_t)n0 * 32;
    const char* srcBl = (const char*)g_Blo + (size_t)n0 * 32;

#define ISSUE(c) do { \
    int _s = (c) & 3; \
    uint32_t _mb = mbarA + _s * 8; \
    uint32_t _st = ab + _s * 16384; \
    MBAR_EXPECT(_mb, 16384u); \
    BULK(_st,          srcAh + (size_t)(c) * 2048 * 32, 4096u, _mb); \
    BULK(_st + 4096,   srcAl + (size_t)(c) * 2048 * 32, 4096u, _mb); \
    BULK(_st + 8192,   srcBh + (size_t)(c) * NV * 32, 4096u, _mb); \
    BULK(_st + 12288,  srcBl + (size_t)(c) * NV * 32, 4096u, _mb); \
} while (0)

    if (tid == 0) {
#pragma unroll
        for (int s = 0; s < 4; s++) ISSUE(s);
    }

    float acc[4][4][4];
#pragma unroll
    for (int mi = 0; mi < 4; mi++)
#pragma unroll
        for (int ni = 0; ni < 4; ni++)
#pragma unroll
            for (int q = 0; q < 4; q++) acc[mi][ni][q] = 0.f;

    for (int c = 0; c < NKC; c++) {
        int s = c & 3;
        MBAR_WAIT(mbarA + s * 8, (c >> 2) & 1);
        const char* Ah = dsg + s * 16384;
        const char* Al = Ah + 4096;
        const char* Bh = Ah + 8192;
        const char* Bl = Ah + 12288;

        uint32_t bh[4][2], bl[4][2];
#pragma unroll
        for (int ni = 0; ni < 4; ni++) {
            const char* bb = Bh + (wn * 32 + ni * 8 + g) * 32 + tg * 4;
            bh[ni][0] = *(const uint32_t*)bb;
            bh[ni][1] = *(const uint32_t*)(bb + 16);
            const char* b2 = Bl + (wn * 32 + ni * 8 + g) * 32 + tg * 4;
            bl[ni][0] = *(const uint32_t*)b2;
            bl[ni][1] = *(const uint32_t*)(b2 + 16);
        }
#pragma unroll
        for (int mi = 0; mi < 4; mi++) {
            const char* aa = Ah + (wm * 64 + mi * 16 + g) * 32 + tg * 4;
            uint32_t ah[4], al[4];
            ah[0] = *(const uint32_t*)aa;
            ah[1] = *(const uint32_t*)(aa + 256);
            ah[2] = *(const uint32_t*)(aa + 16);
            ah[3] = *(const uint32_t*)(aa + 272);
            const char* a2 = Al + (wm * 64 + mi * 16 + g) * 32 + tg * 4;
            al[0] = *(const uint32_t*)a2;
            al[1] = *(const uint32_t*)(a2 + 256);
            al[2] = *(const uint32_t*)(a2 + 16);
            al[3] = *(const uint32_t*)(a2 + 272);
#pragma unroll
            for (int ni = 0; ni < 4; ni++) {
                mma16816(acc[mi][ni], ah, bh[ni]);
                mma16816(acc[mi][ni], ah, bl[ni]);
                mma16816(acc[mi][ni], al, bh[ni]);
            }
        }
        __syncthreads();
        if (tid == 0 && c + 4 < NKC) ISSUE(c + 4);
    }
#undef ISSUE

    // epilogue: +bias, store logits (rows 0-63 -> t=2p, 64-127 -> t=2p+1)
    int tt = 2 * p + wm;
    if (tt < NT) {
#pragma unroll
        for (int mi = 0; mi < 4; mi++) {
            int r0 = (wm * 64 + mi * 16 + g) & 63;
            float* o0 = g_logitsA + ((size_t)tt * NB + r0) * NV + n0;
            float* o1 = g_logitsA + ((size_t)tt * NB + r0 + 8) * NV + n0;
#pragma unroll
            for (int ni = 0; ni < 4; ni++) {
                int cbase = wn * 32 + ni * 8 + tg * 2;
                float2 v0 = make_float2(acc[mi][ni][0] + sb[cbase],
                                        acc[mi][ni][1] + sb[cbase + 1]);
                float2 v1 = make_float2(acc[mi][ni][2] + sb[cbase],
                                        acc[mi][ni][3] + sb[cbase + 1]);
                *(float2*)(o0 + cbase) = v0;
                *(float2*)(o1 + cbase) = v1;
            }
        }
    }
}

// Sampler: R13 epilogue verbatim over stored logits.
__global__ __launch_bounds__(256) void k_samp() {
    const int t = blockIdx.x;
    const int tid = threadIdx.x;
    const int rowg8 = (tid >> 5) * 8;
    const int colg = tid & 31;
    const int n0 = blockIdx.y * 128;
    const int lane = colg;
    uint32_t kk0, kk1;
    tf2x32(0u, 1234u, 0u, (uint32_t)t, kk0, kk1);

    for (int i = 0; i < 8; i++) {
        int rowAbs = rowg8 + i;
        float4 lv = *(const float4*)(g_logitsA + ((size_t)t * NB + rowAbs) * NV + n0 + colg * 4);
        float ll[4] = {lv.x, lv.y, lv.z, lv.w};
        float m = negInf(), S = 0.f, T = 0.f;
        float uu[4], sv[4];
        uint32_t approxMask = 0;
        float rb = negInf();
#pragma unroll
        for (int c = 0; c < 4; c++) {
            float l = ll[c];
            if (S == 0.f) { m = l; S = 1.f; T = 0.f; }
            else if (l > m) {
                float e = expf(m - l);
                T = (T + (m - l) * S) * e;
                S = S * e + 1.f;
                m = l;
            } else {
                float d = l - m, e = expf(d);
                S += e; T += d * e;
            }
            int v = n0 + colg * 4 + c;
            uint32_t o0, o1;
            tf2x32(kk0, kk1, 0u, (uint32_t)(rowAbs * NV + v), o0, o1);
            float u = u01(o0 ^ o1);
            uu[c] = u;
            float af = -__logf(u);
            float s;
            if (af < 1e-4f) {
                s = __fadd_rn(l, exact_g(u));
            } else {
                s = l - __logf(af);
                approxMask |= (1u << c);
            }
            sv[c] = s;
            rb = fmaxf(rb, s);
        }
        for (int o = 16; o; o >>= 1)
            rb = fmaxf(rb, __shfl_xor_sync(0xffffffffu, rb, o));
        float thresh = rb - 4e-3f;

        float best = negInf(), bl = 0.f;
        int bidx = 0x7fffffff;
#pragma unroll
        for (int c = 0; c < 4; c++) {
            float s;
            if (approxMask & (1u << c)) {
                if (sv[c] < thresh) continue;
                s = __fadd_rn(ll[c], exact_g(uu[c]));
            } else {
                s = sv[c];
                if (s < thresh) continue;
            }
            int v = n0 + colg * 4 + c;
            if (s > best || (s == best && v < bidx)) { best = s; bidx = v; bl = ll[c]; }
        }
        for (int o = 16; o; o >>= 1) {
            float m2 = __shfl_down_sync(0xffffffffu, m, o);
            float S2 = __shfl_down_sync(0xffffffffu, S, o);
            float T2 = __shfl_down_sync(0xffffffffu, T, o);
            softmerge(m, S, T, m2, S2, T2);
            float v2 = __shfl_down_sync(0xffffffffu, best, o);
            int   i2 = __shfl_down_sync(0xffffffffu, bidx, o);
            float l2 = __shfl_down_sync(0xffffffffu, bl, o);
            if (v2 > best || (v2 == best && i2 < bidx)) { best = v2; bidx = i2; bl = l2; }
        }
        if (lane == 0) {
            int o = (t * NBLK + blockIdx.y) * NB + rowAbs;
            g_pm[o] = make_float4(m, S, T, 0.f);
            g_pa[o] = make_float4(best, (float)bidx, bl, 0.f);
        }
    }
}

__global__ void k_fin(float* __restrict__ out) {
    int t = blockIdx.x;
    int tid = threadIdx.x, w = tid >> 5, lane = tid & 31;
    for (int row = w; row < NB; row += 8) {
        float m = negInf(), S = 0.f, T = 0.f;
        float best = negInf(), bl = 0.f;
        int bidx = 0x7fffffff;
        for (int b = lane; b < NBLK; b += 32) {
            int o = (t * NBLK + b) * NB + row;
            float4 pm = g_pm[o];
            softmerge(m, S, T, pm.x, pm.y, pm.z);
            float4 pa = g_pa[o];
            int i2 = (int)pa.y;
            if (pa.x > best || (pa.x == best && i2 < bidx)) {
                best = pa.x; bidx = i2; bl = pa.z;
            }
        }
        for (int o = 16; o; o >>= 1) {
            float m2 = __shfl_down_sync(0xffffffffu, m, o);
            float S2 = __shfl_down_sync(0xffffffffu, S, o);
            float T2 = __shfl_down_sync(0xffffffffu, T, o);
            softmerge(m, S, T, m2, S2, T2);
            float v2 = __shfl_down_sync(0xffffffffu, best, o);
            int   i2 = __shfl_down_sync(0xffffffffu, bidx, o);
            float l2 = __shfl_down_sync(0xffffffffu, bl, o);
            if (v2 > best || (v2 == best && i2 < bidx)) { best = v2; bidx = i2; bl = l2; }
        }
        if (lane == 0) {
            float lS = (float)log((double)S);
            out[2 * NB * 2 * NT + row * (2 * NT) + t] = lS - T / S;
            out[row * (2 * NT) + t] = (float)bidx;
            out[NB * 2 * NT + row * (2 * NT) + t] =
                __fadd_rn(__fadd_rn(bl, -m), -lS);
        }
    }
}

__global__ void k_copyh(float* __restrict__ out, const float* __restrict__ h) {
    int i = blockIdx.x * blockDim.x + threadIdx.x;
    if (i < NB * NH) out[3 * NB * 2 * NT + i] = h[i];
}

extern "C" void kernel_launch(void* const* d_in, const int* in_sizes, int n_in,
                              void* d_out, int out_size) {
    const float *inp = 0, *Wx1 = 0, *Wd = 0, *bd = 0, *b1 = 0, *b2 = 0;
    const float* w4[3] = {0, 0, 0};
    int n4 = 0;
    for (int i = 0; i < n_in; i++) {
        const float* p = (const float*)d_in[i];
        switch (in_sizes[i]) {
            case 32768:    inp = p; break;
            case 2097152:  Wx1 = p; break;
            case 4194304:  if (n4 < 3) w4[n4++] = p; break;
            case 32768000: Wd = p; break;
            case 32000:    bd = p; break;
            case 4096:     if (!b1) b1 = p; else b2 = p; break;
            default: break;
        }
    }
    float* out = (float*)d_out;

    void *pw1, *pw2, *phs;
    cudaGetSymbolAddress(&pw1, g_W1p);
    cudaGetSymbolAddress(&pw2, g_W2p);
    cudaGetSymbolAddress(&phs, g_hs);
    float* W1p = (float*)pw1;
    float* W2p = (float*)pw2;
    float* hs  = (float*)phs;

    cudaFuncSetAttribute(gemmF_mma, cudaFuncAttributeMaxDynamicSharedMemorySize,
                         66560);

    k_init<<<256, 256>>>();
    k_init2<<<48, 256>>>(out);
    k_prep<<<16384, 256>>>(Wx1, w4[1], w4[2]);
    k_w2b<<<dim3(1000, 32), dim3(32, 8)>>>(Wd);

    // encoder + decoder state chain (the only sequential dependency)
    gemmG<<<256, 256>>>(inp, W1p, b1, hs, 512);
    for (int t = 0; t < NT; t++)
        gemmG<<<256, 256>>>(hs + (size_t)t * NB * NH, W2p, b2,
                            hs + (size_t)(t + 1) * NB * NH, NH);

    k_h2b<<<8192, 256>>>();
    gemmF_mma<<<dim3(NPAIR, 250), 256, 66560>>>(bd);
    k_samp<<<dim3(NT, NBLK), 256>>>();
    k_fin<<<NT, 256>>>(out);
    k_copyh<<<256, 256>>>(out, hs + (size_t)NT * NB * NH);
}

// round 16
// speedup vs baseline: 1.0191x; 1.0191x over previous
#include <cuda_runtime.h>
#include <stdint.h>
#include <math.h>

#define NB 64
#define NH 1024
#define NV 32000
#define NT 31
#define NBLK 250   // gemmF n-slices (32000/128)

// -------- device scratch --------
__device__ float g_W1p[512 * 4096];     // gate-interleaved Wx1
__device__ float g_W2p[1024 * 4096];    // gate-interleaved Wx2+Wh2
__device__ float g_hs[(NT + 1) * NB * NH];
__device__ float g_c[NB * NH];
__device__ float4 g_pm[NT * NBLK * NB];    // per-block softmax partials (m,S,T)
__device__ float4 g_pa[NT * NBLK * NB];    // per-block argmax partials (best, idx, l)

__device__ __forceinline__ float negInf() { return __int_as_float(0xff800000); }

// ---- packed f32x2 FMA (sm_103a): two independent rn-FMAs per instruction ----
__device__ __forceinline__ unsigned long long pk2(float x) {
    unsigned long long r;
    asm("mov.b64 %0, {%1, %1};" : "=l"(r) : "f"(x));
    return r;
}
__device__ __forceinline__ void fma2(unsigned long long& c, unsigned long long a,
                                     unsigned long long b) {
    asm("fma.rn.f32x2 %0, %1, %2, %0;" : "+l"(c) : "l"(a), "l"(b));
}
__device__ __forceinline__ float lo32(unsigned long long v) {
    return __uint_as_float((unsigned)v);
}
__device__ __forceinline__ float hi32(unsigned long long v) {
    return __uint_as_float((unsigned)(v >> 32));
}

// ---- cp.async (LDGSTS): register-free global->shared pipeline ----
#define CP16(dst, src) \
    asm volatile("cp.async.cg.shared.global [%0], [%1], 16;" :: "r"(dst), "l"(src))
#define CP4(dst, src) \
    asm volatile("cp.async.ca.shared.global [%0], [%1], 4;" :: "r"(dst), "l"(src))
#define CP_COMMIT() asm volatile("cp.async.commit_group;")
#define CP_WAIT6()  asm volatile("cp.async.wait_group 6;")

// exact JAX threefry2x32 (20 rounds)
__device__ __forceinline__ void tf2x32(uint32_t k0, uint32_t k1,
                                       uint32_t x0, uint32_t x1,
                                       uint32_t& o0, uint32_t& o1) {
    uint32_t k2 = k0 ^ k1 ^ 0x1BD11BDAu;
    x0 += k0; x1 += k1;
#define TFR(r) { x0 += x1; x1 = (x1 << (r)) | (x1 >> (32 - (r))); x1 ^= x0; }
    TFR(13) TFR(15) TFR(26) TFR(6)
    x0 += k1; x1 += k2 + 1u;
    TFR(17) TFR(29) TFR(16) TFR(24)
    x0 += k2; x1 += k0 + 2u;
    TFR(13) TFR(15) TFR(26) TFR(6)
    x0 += k0; x1 += k1 + 3u;
    TFR(17) TFR(29) TFR(16) TFR(24)
    x0 += k1; x1 += k2 + 4u;
    TFR(13) TFR(15) TFR(26) TFR(6)
    x0 += k2; x1 += k0 + 5u;
#undef TFR
    o0 = x0; o1 = x1;
}

__device__ __forceinline__ float u01(uint32_t b) {
    float f = __uint_as_float((b >> 9) | 0x3f800000u) - 1.0f;
    return fmaxf(f, 1.17549435e-38f);
}

// exact gumbel increment (bit-identical to R6..R13 formula)
__device__ __forceinline__ float exact_g(float u) {
    return (float)(-log(-log((double)u)));
}

__device__ __forceinline__ void softmerge(float& m, float& S, float& T,
                                          float m2, float S2, float T2) {
    if (S2 == 0.f) return;
    if (S == 0.f) { m = m2; S = S2; T = T2; return; }
    if (m2 > m) {
        float t;
        t = m; m = m2; m2 = t;
        t = S; S = S2; S2 = t;
        t = T; T = T2; T2 = t;
    }
    float e = expf(m2 - m);
    S += S2 * e;
    T += (T2 + (m2 - m) * S2) * e;
}

__global__ void k_init() {
    int i = blockIdx.x * blockDim.x + threadIdx.x;
    if (i < NB * NH) g_c[i] = 0.f;
}
__global__ void k_init2(float* __restrict__ out) {
    int i = blockIdx.x * blockDim.x + threadIdx.x;
    if (i < 3 * NB * 2 * NT) out[i] = 0.f;
}

// Gate-interleave permutation: Wp[k][4j+q] = W[k][q*1024+j]
__global__ void k_prep(const float* __restrict__ Wx1, const float* __restrict__ Wx2,
                       const float* __restrict__ Wh2) {
    int idx = blockIdx.x * blockDim.x + threadIdx.x;   // < 1024*4096
    int k = idx >> 12, col = idx & 4095;
    int j = col >> 2, q = col & 3;
    int src = (k << 12) + (q << 10) + j;
    g_W2p[idx] = Wx2[src] + Wh2[src];
    if (k < 512) g_W1p[idx] = Wx1[src];
}

// Fused gate GEMM + LSTM pointwise. B via 8-stage cp.async ring (wait_group 6:
// 6-chunk slack >> L2/DRAM latency; one group per chunk, empty commits at tail
// keep accounting exact). A via depth-2 register pipeline into 2-buffer smem.
__global__ __launch_bounds__(256, 2) void gemmG(const float* __restrict__ A,
                                                const float* __restrict__ W,
                                                const float* __restrict__ bias,
                                                float* __restrict__ hout,
                                                int K) {
    __shared__ float As[2][16][64];
    __shared__ float Bs[8][16][16];
    const int tid = threadIdx.x;
    const int row = tid & 63;
    const int jj  = tid >> 6;              // 0..3
    const int j0  = blockIdx.x * 4;        // 4 j-states per block
    const int c0  = blockIdx.x * 16;       // 16 permuted cols per block
    const int ar = tid >> 2, ak = (tid & 3) * 4;
    const int kr = tid >> 4, cc = tid & 15;     // B scalar staging
    const int NC = K / 16;

    unsigned long long aif = 0, ago = 0;

    const float* bsrc = W + (size_t)kr * 4096 + c0 + cc;
    uint32_t bBase = (uint32_t)__cvta_generic_to_shared(&Bs[0][kr][cc]);

    // prolog: B groups for chunks 0..6 (empty commit when past NC)
#pragma unroll
    for (int s = 0; s < 7; s++) {
        if (s < NC) CP4(bBase + s * 1024, bsrc + (size_t)s * 16 * 4096);
        CP_COMMIT();
    }
    float4 paN;
    {
        float4 p0 = *(const float4*)(A + ar * K + ak);
        As[0][ak + 0][ar] = p0.x; As[0][ak + 1][ar] = p0.y;
        As[0][ak + 2][ar] = p0.z; As[0][ak + 3][ar] = p0.w;
        paN = *(const float4*)(A + ar * K + 16 + ak);
    }

    for (int c = 0; c < NC; c++) {
        CP_WAIT6();            // group c complete (pending <= groups c+1..c+6)
        __syncthreads();
        if (c + 1 < NC) {
            int b = (c + 1) & 1;
            As[b][ak + 0][ar] = paN.x; As[b][ak + 1][ar] = paN.y;
            As[b][ak + 2][ar] = paN.z; As[b][ak + 3][ar] = paN.w;
        }
        if (c + 2 < NC) paN = *(const float4*)(A + ar * K + (c + 2) * 16 + ak);
        if (c + 7 < NC) CP4(bBase + ((c + 7) & 7) * 1024,
                            bsrc + (size_t)(c + 7) * 16 * 4096);
        CP_COMMIT();
        int cur = c & 1, cb = c & 7;
#pragma unroll
        for (int k = 0; k < 16; k++) {
            unsigned long long ap = pk2(As[cur][k][row]);
            ulonglong2 bA = *(const ulonglong2*)&Bs[cb][k][jj * 4];
            fma2(aif, ap, bA.x);
            fma2(ago, ap, bA.y);
        }
    }

    int j = j0 + jj;
    float zi = __fadd_rn(lo32(aif), bias[j]);
    float zf = __fadd_rn(hi32(aif), bias[1024 + j]);
    float zg = __fadd_rn(lo32(ago), bias[2048 + j]);
    float zo = __fadd_rn(hi32(ago), bias[3072 + j]);
    float si = 1.f / (1.f + expf(-zi));
    float sf = 1.f / (1.f + expf(-zf));
    float so = 1.f / (1.f + expf(-zo));
    int ci = row * NH + j;
    float cn = __fadd_rn(__fmul_rn(sf, g_c[ci]), __fmul_rn(si, zg));
    g_c[ci] = cn;
    hout[ci] = __fmul_rn(so, cn);
}

// ALL 31 steps' logits GEMM + softmax partials + gumbel sampling.
// Tile 64x128, 3 blocks/SM. B via 8-stage cp.async ring (wait_group 6,
// 6-chunk slack ~1500cyc covers DRAM), A depth-2 regs. Dynamic smem:
// As 2x[16][64] at offset 0, Bs 8x[16][128] at 8KB. K-order per element
// identical to R13 -> logits bit-identical. Barrier-free warp-row epilogue.
__global__ __launch_bounds__(256, 3) void gemmF(const float* __restrict__ hs,
                                                const float* __restrict__ B,
                                                const float* __restrict__ bias) {
    extern __shared__ float dsm[];
    float* AsP = dsm;            // [2][16][64]
    float* BsP = dsm + 2048;     // [8][16][128]
#define ASF(b, k, r) AsP[(b) * 1024 + (k) * 64 + (r)]
#define BSF(s, k, cix) BsP[(s) * 2048 + (k) * 128 + (cix)]
    const int t = blockIdx.x;
    const float* A = hs + (size_t)(t + 1) * NB * NH;
    const int tid = threadIdx.x;
    const int rowg8 = (tid >> 5) * 8;  // warp owns rows rowg8..rowg8+7
    const int colg = tid & 31;         // lane owns cols colg*4..+3
    const int n0 = blockIdx.y * 128;
    const int lane = colg;
    const int ar = tid >> 2, ak = (tid & 3) * 4;
    const int bk = tid >> 4, bc = (tid & 15) * 8;

    unsigned long long acc[4][4];   // [row-pair][col]
#pragma unroll
    for (int p = 0; p < 4; p++)
#pragma unroll
        for (int c = 0; c < 4; c++) acc[p][c] = 0ull;

    const float* bsrc = B + (size_t)bk * NV + n0 + bc;
    uint32_t bBase = (uint32_t)__cvta_generic_to_shared(&BSF(0, bk, bc));

    // prolog: B groups for chunks 0..6
#pragma unroll
    for (int s = 0; s < 7; s++) {
        CP16(bBase + s * 8192, bsrc + (size_t)s * 16 * NV);
        CP16(bBase + s * 8192 + 16, bsrc + (size_t)s * 16 * NV + 4);
        CP_COMMIT();
    }
    float4 paN;
    {
        float4 p0 = *(const float4*)(A + ar * NH + ak);
        ASF(0, ak + 0, ar) = p0.x; ASF(0, ak + 1, ar) = p0.y;
        ASF(0, ak + 2, ar) = p0.z; ASF(0, ak + 3, ar) = p0.w;
        paN = *(const float4*)(A + ar * NH + 16 + ak);
    }

    for (int c = 0; c < 64; c++) {
        CP_WAIT6();
        __syncthreads();
        if (c + 1 < 64) {
            int b = (c + 1) & 1;
            ASF(b, ak + 0, ar) = paN.x; ASF(b, ak + 1, ar) = paN.y;
            ASF(b, ak + 2, ar) = paN.z; ASF(b, ak + 3, ar) = paN.w;
        }
        if (c + 2 < 64) paN = *(const float4*)(A + ar * NH + (c + 2) * 16 + ak);
        if (c + 7 < 64) {
            uint32_t d = bBase + ((c + 7) & 7) * 8192;
            const float* s = bsrc + (size_t)(c + 7) * 16 * NV;
            CP16(d, s);
            CP16(d + 16, s + 4);
        }
        CP_COMMIT();
        int cur = c & 1, cb = c & 7;
#pragma unroll
        for (int k = 0; k < 16; k++) {
            ulonglong2 a01 = *(const ulonglong2*)&ASF(cur, k, rowg8);
            ulonglong2 a23 = *(const ulonglong2*)&ASF(cur, k, rowg8 + 4);
            float4 bv = *(const float4*)&BSF(cb, k, colg * 4);
            unsigned long long b0 = pk2(bv.x), b1 = pk2(bv.y);
            unsigned long long b2 = pk2(bv.z), b3 = pk2(bv.w);
            fma2(acc[0][0], a01.x, b0); fma2(acc[0][1], a01.x, b1);
            fma2(acc[0][2], a01.x, b2); fma2(acc[0][3], a01.x, b3);
            fma2(acc[1][0], a01.y, b0); fma2(acc[1][1], a01.y, b1);
            fma2(acc[1][2], a01.y, b2); fma2(acc[1][3], a01.y, b3);
            fma2(acc[2][0], a23.x, b0); fma2(acc[2][1], a23.x, b1);
            fma2(acc[2][2], a23.x, b2); fma2(acc[2][3], a23.x, b3);
            fma2(acc[3][0], a23.y, b0); fma2(acc[3][1], a23.y, b1);
            fma2(acc[3][2], a23.y, b2); fma2(acc[3][3], a23.y, b3);
        }
    }
#undef ASF
#undef BSF

    // ---- barrier-free epilogue: warp-complete rows (unchanged from R13) ----
    float bcol[4];
#pragma unroll
    for (int c = 0; c < 4; c++) bcol[c] = bias[n0 + colg * 4 + c];
    uint32_t kk0, kk1;
    tf2x32(0u, 1234u, 0u, (uint32_t)t, kk0, kk1);   // fold_in(key(1234), t)

    for (int i = 0; i < 8; i++) {
        int p = i >> 1;
        int rowAbs = rowg8 + i;
        float m = negInf(), S = 0.f, T = 0.f;

        float ll[4], uu[4], sv[4];
        uint32_t approxMask = 0;
        float rb = negInf();
#pragma unroll
        for (int c = 0; c < 4; c++) {
            float l = __fadd_rn((i & 1) ? hi32(acc[p][c]) : lo32(acc[p][c]), bcol[c]);
            ll[c] = l;
            if (S == 0.f) { m = l; S = 1.f; T = 0.f; }
            else if (l > m) {
                float e = expf(m - l);
                T = (T + (m - l) * S) * e;
                S = S * e + 1.f;
                m = l;
            } else {
                float d = l - m, e = expf(d);
                S += e; T += d * e;
            }
            int v = n0 + colg * 4 + c;
            uint32_t o0, o1;
            tf2x32(kk0, kk1, 0u, (uint32_t)(rowAbs * NV + v), o0, o1);
            float u = u01(o0 ^ o1);
            uu[c] = u;
            float af = -__logf(u);
            float s;
            if (af < 1e-4f) {
                s = __fadd_rn(l, exact_g(u));       // exact now (tail, likely winner)
            } else {
                s = l - __logf(af);                 // fast approx
                approxMask |= (1u << c);
            }
            sv[c] = s;
            rb = fmaxf(rb, s);
        }
        for (int o = 16; o; o >>= 1)
            rb = fmaxf(rb, __shfl_xor_sync(0xffffffffu, rb, o));
        float thresh = rb - 4e-3f;

        float best = negInf(), bl = 0.f;
        int bidx = 0x7fffffff;
#pragma unroll
        for (int c = 0; c < 4; c++) {
            float s;
            if (approxMask & (1u << c)) {
                if (sv[c] < thresh) continue;
                s = __fadd_rn(ll[c], exact_g(uu[c]));
            } else {
                s = sv[c];
                if (s < thresh) continue;
            }
            int v = n0 + colg * 4 + c;
            if (s > best || (s == best && v < bidx)) { best = s; bidx = v; bl = ll[c]; }
        }
        for (int o = 16; o; o >>= 1) {
            float m2 = __shfl_down_sync(0xffffffffu, m, o);
            float S2 = __shfl_down_sync(0xffffffffu, S, o);
            float T2 = __shfl_down_sync(0xffffffffu, T, o);
            softmerge(m, S, T, m2, S2, T2);
            float v2 = __shfl_down_sync(0xffffffffu, best, o);
            int   i2 = __shfl_down_sync(0xffffffffu, bidx, o);
            float l2 = __shfl_down_sync(0xffffffffu, bl, o);
            if (v2 > best || (v2 == best && i2 < bidx)) { best = v2; bidx = i2; bl = l2; }
        }
        if (lane == 0) {
            int o = (t * NBLK + blockIdx.y) * NB + rowAbs;
            g_pm[o] = make_float4(m, S, T, 0.f);
            g_pa[o] = make_float4(best, (float)bidx, bl, 0.f);
        }
    }
}

// Final merge over the 250 block partials, all 31 steps at once.
__global__ void k_fin(float* __restrict__ out) {
    int t = blockIdx.x;
    int tid = threadIdx.x, w = tid >> 5, lane = tid & 31;
    for (int row = w; row < NB; row += 8) {
        float m = negInf(), S = 0.f, T = 0.f;
        float best = negInf(), bl = 0.f;
        int bidx = 0x7fffffff;
        for (int b = lane; b < NBLK; b += 32) {
            int o = (t * NBLK + b) * NB + row;
            float4 pm = g_pm[o];
            softmerge(m, S, T, pm.x, pm.y, pm.z);
            float4 pa = g_pa[o];
            int i2 = (int)pa.y;
            if (pa.x > best || (pa.x == best && i2 < bidx)) {
                best = pa.x; bidx = i2; bl = pa.z;
            }
        }
        for (int o = 16; o; o >>= 1) {
            float m2 = __shfl_down_sync(0xffffffffu, m, o);
            float S2 = __shfl_down_sync(0xffffffffu, S, o);
            float T2 = __shfl_down_sync(0xffffffffu, T, o);
            softmerge(m, S, T, m2, S2, T2);
            float v2 = __shfl_down_sync(0xffffffffu, best, o);
            int   i2 = __shfl_down_sync(0xffffffffu, bidx, o);
            float l2 = __shfl_down_sync(0xffffffffu, bl, o);
            if (v2 > best || (v2 == best && i2 < bidx)) { best = v2; bidx = i2; bl = l2; }
        }
        if (lane == 0) {
            float lS = (float)log((double)S);
            out[2 * NB * 2 * NT + row * (2 * NT) + t] = lS - T / S;   // entropy
            out[row * (2 * NT) + t] = (float)bidx;                    // msg
            out[NB * 2 * NT + row * (2 * NT) + t] =
                __fadd_rn(__fadd_rn(bl, -m), -lS);                    // log_prob
        }
    }
}

__global__ void k_copyh(float* __restrict__ out, const float* __restrict__ h) {
    int i = blockIdx.x * blockDim.x + threadIdx.x;
    if (i < NB * NH) out[3 * NB * 2 * NT + i] = h[i];
}

extern "C" void kernel_launch(void* const* d_in, const int* in_sizes, int n_in,
                              void* d_out, int out_size) {
    // Size-based dispatch (robust to metadata ordering):
    const float *inp = 0, *Wx1 = 0, *Wd = 0, *bd = 0, *b1 = 0, *b2 = 0;
    const float* w4[3] = {0, 0, 0};
    int n4 = 0;
    for (int i = 0; i < n_in; i++) {
        const float* p = (const float*)d_in[i];
        switch (in_sizes[i]) {
            case 32768:    inp = p; break;
            case 2097152:  Wx1 = p; break;
            case 4194304:  if (n4 < 3) w4[n4++] = p; break;   // Wh1(unused), Wx2, Wh2
            case 32768000: Wd = p; break;
            case 32000:    bd = p; break;
            case 4096:     if (!b1) b1 = p; else b2 = p; break;
            default: break;
        }
    }
    float* out = (float*)d_out;

    void *pw1, *pw2, *phs;
    cudaGetSymbolAddress(&pw1, g_W1p);
    cudaGetSymbolAddress(&pw2, g_W2p);
    cudaGetSymbolAddress(&phs, g_hs);
    float* W1p = (float*)pw1;
    float* W2p = (float*)pw2;
    float* hs  = (float*)phs;

    cudaFuncSetAttribute(gemmF, cudaFuncAttributeMaxDynamicSharedMemorySize, 73728);

    k_init<<<256, 256>>>();
    k_init2<<<48, 256>>>(out);
    k_prep<<<16384, 256>>>(Wx1, w4[1], w4[2]);

    // encoder: one step, zero state -> hs[0]
    gemmG<<<256, 256>>>(inp, W1p, b1, hs, 512);

    // decoder state chain (the only sequential dependency)
    for (int t = 0; t < NT; t++)
        gemmG<<<256, 256>>>(hs + (size_t)t * NB * NH, W2p, b2,
                            hs + (size_t)(t + 1) * NB * NH, NH);

    // all 31 logits+sampling GEMMs in one wave-parallel launch
    gemmF<<<dim3(NT, NBLK), 256, 73728>>>(hs, Wd, bd);

    k_fin<<<NT, 256>>>(out);
    k_copyh<<<256, 256>>>(out, hs + (size_t)NT * NB * NH);
}